// round 5
// baseline (speedup 1.0000x reference)
#include <cuda_runtime.h>
#include <cuda_bf16.h>
#include <cstdint>
#include <cstddef>

#define NROWS 131072
#define NSEQ 64
#define TSTEPS 2048

// ---------------- scratch ----------------
__device__ __align__(16) float g_WcatHi[2048 * 256];
__device__ __align__(16) float g_WcatLo[2048 * 256];
__device__ float g_bcat[2048];
__device__ __align__(16) uint4 g_WpackH[128 * 256];
__device__ float g_Wp2T[512 * 32];
__device__ __align__(16) float g_Wp1Hi[512 * 1024];
__device__ __align__(16) float g_Wp1Lo[512 * 1024];
__device__ __align__(16) float g_Wv1Hi[512 * 1024];
__device__ __align__(16) float g_Wv1Lo[512 * 1024];
__device__ __align__(16) float g_f1[(size_t)NROWS * 768];
__device__ __align__(16) float g_opi[(size_t)NROWS * 256];
__device__ __align__(16) float g_xg[(size_t)NROWS * 1024];   // reused as HP/HV after LSTM
__device__ __align__(16) float g_hs[(size_t)NROWS * 256];
__device__ int g_fixctr;
__device__ int g_fixlist[65536];

// ---------------- helpers ----------------
__device__ __forceinline__ unsigned long long ffma2(unsigned long long a, unsigned long long b, unsigned long long c) {
    asm("fma.rn.f32x2 %0, %1, %2, %3;" : "=l"(c) : "l"(a), "l"(b), "l"(c));
    return c;
}
__device__ __forceinline__ void unpack2(unsigned long long v, float& a, float& b) {
    asm("mov.b64 {%0, %1}, %2;" : "=f"(a), "=f"(b) : "l"(v));
}
__device__ __forceinline__ unsigned long long pack2b(unsigned lo, unsigned hi) {
    unsigned long long r;
    asm("mov.b64 %0, {%1, %2};" : "=l"(r) : "r"(lo), "r"(hi));
    return r;
}
__device__ __forceinline__ unsigned long long bfexp(unsigned r) {
    return pack2b(r << 16, r & 0xffff0000u);
}
__device__ __forceinline__ float sigf(float x) { return __fdividef(1.f, 1.f + __expf(-x)); }
__device__ __forceinline__ float tanha(float x) {
    float y;
    asm("tanh.approx.f32 %0, %1;" : "=f"(y) : "f"(x));
    return y;
}
__device__ __forceinline__ void split_tf32(float x, uint32_t& h, uint32_t& l) {
    asm("cvt.rna.tf32.f32 %0, %1;" : "=r"(h) : "f"(x));
    float lo = x - __uint_as_float(h);
    asm("cvt.rna.tf32.f32 %0, %1;" : "=r"(l) : "f"(lo));
}
__device__ __forceinline__ void mma_tf32(float* d, const uint32_t* a, const uint32_t* b) {
    asm volatile(
        "mma.sync.aligned.m16n8k8.row.col.f32.tf32.tf32.f32 "
        "{%0,%1,%2,%3}, {%4,%5,%6,%7}, {%8,%9}, {%0,%1,%2,%3};"
        : "+f"(d[0]), "+f"(d[1]), "+f"(d[2]), "+f"(d[3])
        : "r"(a[0]), "r"(a[1]), "r"(a[2]), "r"(a[3]), "r"(b[0]), "r"(b[1]));
}

// ---------------- prep ----------------
__global__ void prep_kernel(const float* __restrict__ W_feat, const float* __restrict__ b_feat,
                            const float* __restrict__ W_emb, const float* __restrict__ b_emb,
                            const float* __restrict__ W_ih, const float* __restrict__ W_hh,
                            const float* __restrict__ b_ih, const float* __restrict__ b_hh,
                            const float* __restrict__ Wp2) {
    int i = blockIdx.x * 256 + threadIdx.x;   // up to 524288
    {
        int r = i >> 8;
        float wv;
        if (r < 768) wv = W_feat[i];
        else if (r < 1024) wv = W_emb[i - 768 * 256];
        else wv = W_ih[i - 1024 * 256];
        uint32_t h, l;
        split_tf32(wv, h, l);
        g_WcatHi[i] = __uint_as_float(h);
        g_WcatLo[i] = __uint_as_float(l);
    }
    if (i < 2048) {
        float b;
        if (i < 768) b = b_feat[i];
        else if (i < 1024) b = b_emb[i - 768];
        else b = b_ih[i - 1024] + b_hh[i - 1024];
        g_bcat[i] = b;
    }
    if (i < 65536) {
        int kk = i >> 8, k = i & 255;
        float wi = W_hh[(0 + k) * 256 + kk];
        float wf = W_hh[(256 + k) * 256 + kk];
        float wg = W_hh[(512 + k) * 256 + kk];
        float wo = W_hh[(768 + k) * 256 + kk];
        __nv_bfloat162 bif = __floats2bfloat162_rn(wi, wf);
        __nv_bfloat162 bgo = __floats2bfloat162_rn(wg, wo);
        unsigned uif = *(unsigned*)&bif;
        unsigned ugo = *(unsigned*)&bgo;
        int kk2 = kk >> 1, half = kk & 1;
        ((uint2*)g_WpackH)[(kk2 << 9) + (k << 1) + half] = make_uint2(uif, ugo);
    }
    if (i < 16384) {
        int j = i >> 5, a = i & 31;
        g_Wp2T[i] = Wp2[a * 512 + j];
    }
}

__global__ void wsplit_kernel(const float* __restrict__ Wp1, const float* __restrict__ Wv1) {
    int i = blockIdx.x * 256 + threadIdx.x;   // up to 1048576
    uint32_t h, l;
    if (i < 524288) {
        split_tf32(Wp1[i], h, l);
        g_Wp1Hi[i] = __uint_as_float(h);
        g_Wp1Lo[i] = __uint_as_float(l);
    } else {
        int j = i - 524288;
        split_tf32(Wv1[j], h, l);
        g_Wv1Hi[j] = __uint_as_float(h);
        g_Wv1Lo[j] = __uint_as_float(l);
    }
}

__global__ void zero_ctr() { if (threadIdx.x == 0) g_fixctr = 0; }

// ---------------- h_pi/c_pi masked passthrough ----------------
__global__ void hpi_kernel(const float* __restrict__ starts, const float* __restrict__ h_pi,
                           const float* __restrict__ c_pi, float* __restrict__ out) {
    int s = blockIdx.x, tid = threadIdx.x;
    __shared__ float red[256];
    float p = 1.f;
    for (int t = tid; t < TSTEPS; t += 256) p *= (1.f - starts[s * TSTEPS + t]);
    red[tid] = p;
    __syncthreads();
    for (int st = 128; st; st >>= 1) {
        if (tid < st) red[tid] *= red[tid + st];
        __syncthreads();
    }
    float m = red[0];
    size_t base = (size_t)3 * NROWS;
    out[base + s * 256 + tid] = h_pi[s * 256 + tid] * m;
    out[base + 16384 + s * 256 + tid] = c_pi[s * 256 + tid] * m;
}

// ---------------- mma.sync tf32-split GEMM ----------------
#define PADK 20

template <int MODE>
__global__ void __launch_bounds__(256, 1) mma_gemm(
    const float* __restrict__ A0, const float* __restrict__ A1,
    int K0, int Ktot, int lda0, int lda1,
    const float* __restrict__ WHi, const float* __restrict__ WLo, int ldw,
    const float* __restrict__ bias,
    float* __restrict__ C0, float* __restrict__ C1, float* __restrict__ C2) {
    __shared__ __align__(16) float smem[4 * 128 * PADK];  // 40960 B
    float* sAh = smem;
    float* sAl = smem + 128 * PADK;
    float* sBh = smem + 2 * 128 * PADK;
    float* sBl = smem + 3 * 128 * PADK;

    int tid = threadIdx.x, lane = tid & 31, wid = tid >> 5;
    int wr = wid >> 2, wc = wid & 3;
    int rowBase = blockIdx.y * 128, colBase = blockIdx.x * 128;

    float acc[4][4][4];
#pragma unroll
    for (int a = 0; a < 4; a++)
#pragma unroll
        for (int b = 0; b < 4; b++)
#pragma unroll
            for (int c = 0; c < 4; c++) acc[a][b][c] = 0.f;

    int rowL = tid >> 1, colL = (tid & 1) * 8;
    const int nK = Ktot / 16;

    for (int kt = 0; kt < nK; kt++) {
        int kb = kt * 16;
        const float* Asrc;
        int lda, kloc;
        if (kb < K0) { Asrc = A0; lda = lda0; kloc = kb; }
        else { Asrc = A1; lda = lda1; kloc = kb - K0; }
        const float* ap = Asrc + (size_t)(rowBase + rowL) * lda + kloc + colL;
        const float* bhp = WHi + (size_t)(colBase + rowL) * ldw + kb + colL;
        const float* blp = WLo + (size_t)(colBase + rowL) * ldw + kb + colL;
#pragma unroll
        for (int q = 0; q < 2; q++) {
            float4 v = *(const float4*)(ap + q * 4);
            uint32_t h0, l0, h1, l1, h2, l2, h3, l3;
            split_tf32(v.x, h0, l0);
            split_tf32(v.y, h1, l1);
            split_tf32(v.z, h2, l2);
            split_tf32(v.w, h3, l3);
            int off = rowL * PADK + colL + q * 4;
            *(uint4*)&sAh[off] = make_uint4(h0, h1, h2, h3);
            *(uint4*)&sAl[off] = make_uint4(l0, l1, l2, l3);
        }
#pragma unroll
        for (int q = 0; q < 2; q++) {
            int off = rowL * PADK + colL + q * 4;
            *(float4*)&sBh[off] = *(const float4*)(bhp + q * 4);
            *(float4*)&sBl[off] = *(const float4*)(blp + q * 4);
        }
        __syncthreads();

#pragma unroll
        for (int ks = 0; ks < 2; ks++) {
            int kcol = ks * 8 + (lane & 3);
            uint32_t bh4[4][2], bl4[4][2];
#pragma unroll
            for (int ni = 0; ni < 4; ni++) {
                int nrow = wc * 32 + ni * 8 + (lane >> 2);
                bh4[ni][0] = __float_as_uint(sBh[nrow * PADK + kcol]);
                bh4[ni][1] = __float_as_uint(sBh[nrow * PADK + kcol + 4]);
                bl4[ni][0] = __float_as_uint(sBl[nrow * PADK + kcol]);
                bl4[ni][1] = __float_as_uint(sBl[nrow * PADK + kcol + 4]);
            }
#pragma unroll
            for (int mi = 0; mi < 4; mi++) {
                int mrow = wr * 64 + mi * 16 + (lane >> 2);
                uint32_t ah[4], al[4];
                ah[0] = __float_as_uint(sAh[mrow * PADK + kcol]);
                ah[1] = __float_as_uint(sAh[(mrow + 8) * PADK + kcol]);
                ah[2] = __float_as_uint(sAh[mrow * PADK + kcol + 4]);
                ah[3] = __float_as_uint(sAh[(mrow + 8) * PADK + kcol + 4]);
                al[0] = __float_as_uint(sAl[mrow * PADK + kcol]);
                al[1] = __float_as_uint(sAl[(mrow + 8) * PADK + kcol]);
                al[2] = __float_as_uint(sAl[mrow * PADK + kcol + 4]);
                al[3] = __float_as_uint(sAl[(mrow + 8) * PADK + kcol + 4]);
#pragma unroll
                for (int ni = 0; ni < 4; ni++) {
                    mma_tf32(acc[mi][ni], al, bh4[ni]);
                    mma_tf32(acc[mi][ni], ah, bl4[ni]);
                    mma_tf32(acc[mi][ni], ah, bh4[ni]);
                }
            }
        }
        __syncthreads();
    }

    // ---- epilogue: stage through smem (reuse operand buffers), 2 half-phases ----
    float* T = smem;   // 64 x 132
#pragma unroll
    for (int ph = 0; ph < 2; ph++) {
        if (wr == ph) {
#pragma unroll
            for (int mi = 0; mi < 4; mi++) {
#pragma unroll
                for (int ni = 0; ni < 4; ni++) {
                    int r0 = mi * 16 + (lane >> 2);
                    int cc = wc * 32 + ni * 8 + (lane & 3) * 2;
                    *(float2*)&T[r0 * 132 + cc] = make_float2(acc[mi][ni][0], acc[mi][ni][1]);
                    *(float2*)&T[(r0 + 8) * 132 + cc] = make_float2(acc[mi][ni][2], acc[mi][ni][3]);
                }
            }
        }
        __syncthreads();
#pragma unroll
        for (int i = 0; i < 8; i++) {
            int lin = tid + i * 256;
            int rr = lin >> 5, c4 = (lin & 31) * 4;
            float4 v = *(float4*)&T[rr * 132 + c4];
            float4 bv = *(const float4*)&bias[colBase + c4];
            v.x += bv.x; v.y += bv.y; v.z += bv.z; v.w += bv.w;
            int n = rowBase + ph * 64 + rr;
            int c = colBase + c4;
            if (MODE == 1) {
                v.x = fmaxf(v.x, 0.f); v.y = fmaxf(v.y, 0.f); v.z = fmaxf(v.z, 0.f); v.w = fmaxf(v.w, 0.f);
                *(float4*)&C0[((size_t)n << 9) + c] = v;
            } else {
                if (colBase < 768) *(float4*)&C0[(size_t)n * 768 + c] = v;
                else if (colBase < 1024) *(float4*)&C1[(size_t)n * 256 + (c - 768)] = v;
                else {
                    int sq = n >> 11, tt = n & 2047;
                    *(float4*)&C2[((size_t)((tt << 6) | sq) << 10) + (c - 1024)] = v;
                }
            }
        }
        __syncthreads();
    }
}

// ---------------- LSTM scan: one CTA per sequence, bf16 W ----------------
__global__ void __launch_bounds__(256) lstm_kernel(
    const float* __restrict__ starts, const float* __restrict__ h0,
    const float* __restrict__ c0v, const uint4* __restrict__ WpH,
    const float* __restrict__ xg, float* __restrict__ hs,
    float* __restrict__ out) {
    int s = blockIdx.x, k = threadIdx.x;
    __shared__ __align__(16) float2 hbuf[2][256];
    float c = c0v[s * 256 + k];
    float h = h0[s * 256 + k];
    hbuf[0][k] = make_float2(h, h);
    __syncthreads();
    int cur = 0;
    float hn = h;
    for (int t = 0; t < TSTEPS; t++) {
        float m = 1.0f - starts[s * TSTEPS + t];
        const float* xgp = xg + ((size_t)(t * 64 + s) << 10);
        unsigned long long aif = 0ULL, ago = 0ULL;
        const ulonglong2* hb2 = (const ulonglong2*)hbuf[cur];
#pragma unroll 8
        for (int kk2 = 0; kk2 < 128; kk2++) {
            uint4 w = WpH[(kk2 << 8) + k];
            ulonglong2 hh = hb2[kk2];
            aif = ffma2(bfexp(w.x), hh.x, aif);
            ago = ffma2(bfexp(w.y), hh.x, ago);
            aif = ffma2(bfexp(w.z), hh.y, aif);
            ago = ffma2(bfexp(w.w), hh.y, ago);
        }
        float di, df, dg, dq;
        unpack2(aif, di, df);
        unpack2(ago, dg, dq);
        float gi = xgp[k] + m * di;
        float gf = xgp[256 + k] + m * df;
        float gg = xgp[512 + k] + m * dg;
        float go = xgp[768 + k] + m * dq;
        c *= m;
        c = sigf(gf) * c + sigf(gi) * tanha(gg);
        hn = sigf(go) * tanha(c);
        hs[((size_t)s * TSTEPS + t) * 256 + k] = hn;
        hbuf[cur ^ 1][k] = make_float2(hn, hn);
        cur ^= 1;
        __syncthreads();
    }
    size_t base = (size_t)3 * NROWS;
    out[base + 32768 + s * 256 + k] = hn;
    out[base + 49152 + s * 256 + k] = c;
}

// ---------------- final: logits, argmax, log_prob, value, near-tie flag ----------------
__global__ void __launch_bounds__(256) head_final(
    const float* __restrict__ HP, const float* __restrict__ HV,
    const float* __restrict__ bp2, const float* __restrict__ Wv2,
    const float* __restrict__ bv2, const float* __restrict__ Wp2T,
    float* __restrict__ out) {
    extern __shared__ float sm[];
    float* sW = sm;            // 16384
    float* sRow = sm + 16384;  // 8*512
    int tid = threadIdx.x, lane = tid & 31, w = tid >> 5;
    for (int i = tid; i < 16384; i += 256) sW[i] = Wp2T[i];
    __syncthreads();
    int n = blockIdx.x * 8 + w;

#pragma unroll
    for (int i = 0; i < 16; i++) sRow[w * 512 + i * 32 + lane] = HP[((size_t)n << 9) + i * 32 + lane];
    __syncwarp();

    float acc = bp2[lane];
    const float* r = &sRow[w * 512];
#pragma unroll 8
    for (int j = 0; j < 512; j++) acc = fmaf(sW[j * 32 + lane], r[j], acc);

    float vacc = 0.f;
#pragma unroll
    for (int i = 0; i < 16; i++) vacc = fmaf(Wv2[i * 32 + lane], HV[((size_t)n << 9) + i * 32 + lane], vacc);
#pragma unroll
    for (int o = 16; o; o >>= 1) vacc += __shfl_xor_sync(0xffffffffu, vacc, o);

    float l = acc;
    float mx = l;
#pragma unroll
    for (int o = 16; o; o >>= 1) mx = fmaxf(mx, __shfl_xor_sync(0xffffffffu, mx, o));
    int best = (l == mx) ? lane : 64;
#pragma unroll
    for (int o = 16; o; o >>= 1) best = min(best, __shfl_xor_sync(0xffffffffu, best, o));
    float e = expf(l - mx);
#pragma unroll
    for (int o = 16; o; o >>= 1) e += __shfl_xor_sync(0xffffffffu, e, o);

    // second max (excluding the argmax lane) for near-tie detection
    float lnb = (lane == best) ? -1e30f : l;
#pragma unroll
    for (int o = 16; o; o >>= 1) lnb = fmaxf(lnb, __shfl_xor_sync(0xffffffffu, lnb, o));

    if (lane == 0) {
        out[n] = (float)best;
        out[NROWS + n] = vacc + bv2[0];
        out[2 * NROWS + n] = -logf(e);
        if (mx - lnb < 1e-4f) {
            int id = atomicAdd(&g_fixctr, 1);
            if (id < 65536) g_fixlist[id] = n;
        }
    }
}

// ---------------- fixup: exact fp32 policy chain for near-tie rows ----------------
__global__ void __launch_bounds__(256) fixup_kernel(
    const float* __restrict__ features,
    const float* __restrict__ W_feat, const float* __restrict__ b_feat,
    const float* __restrict__ W_emb, const float* __restrict__ b_emb,
    const float* __restrict__ Wp1, const float* __restrict__ bp1,
    const float* __restrict__ Wp2, const float* __restrict__ bp2,
    float* __restrict__ out) {
    __shared__ float sx[256];
    __shared__ float lat[1024];
    __shared__ float hp[512];
    __shared__ float lg[32];
    int tid = threadIdx.x, lane = tid & 31, w = tid >> 5;
    int cnt = g_fixctr;
    if (cnt > 65536) cnt = 65536;
    for (int idx = blockIdx.x; idx < cnt; idx += gridDim.x) {
        int n = g_fixlist[idx];
        sx[tid] = features[(size_t)n * 256 + tid];
        __syncthreads();
#pragma unroll
        for (int q = 0; q < 4; q++) {
            int j = tid + q * 256;
            const float* wr;
            float a;
            if (j < 768) { wr = W_feat + (size_t)j * 256; a = b_feat[j]; }
            else { wr = W_emb + (size_t)(j - 768) * 256; a = b_emb[j - 768]; }
            for (int k = 0; k < 256; k++) a = fmaf(wr[k], sx[k], a);
            lat[j] = a;
        }
        __syncthreads();
#pragma unroll
        for (int q = 0; q < 2; q++) {
            int j = tid + q * 256;
            const float* wr = Wp1 + (size_t)j * 1024;
            float a = bp1[j];
            for (int k = 0; k < 1024; k++) a = fmaf(wr[k], lat[k], a);
            hp[j] = fmaxf(a, 0.f);
        }
        __syncthreads();
#pragma unroll
        for (int q = 0; q < 4; q++) {
            int ai = w * 4 + q;
            const float* wr = Wp2 + (size_t)ai * 512;
            float p = 0.f;
            for (int k = lane; k < 512; k += 32) p = fmaf(wr[k], hp[k], p);
#pragma unroll
            for (int o = 16; o; o >>= 1) p += __shfl_xor_sync(0xffffffffu, p, o);
            if (lane == 0) lg[ai] = p + bp2[ai];
        }
        __syncthreads();
        if (w == 0) {
            float l = lg[lane];
            float mx = l;
#pragma unroll
            for (int o = 16; o; o >>= 1) mx = fmaxf(mx, __shfl_xor_sync(0xffffffffu, mx, o));
            int best = (l == mx) ? lane : 64;
#pragma unroll
            for (int o = 16; o; o >>= 1) best = min(best, __shfl_xor_sync(0xffffffffu, best, o));
            float e = expf(l - mx);
#pragma unroll
            for (int o = 16; o; o >>= 1) e += __shfl_xor_sync(0xffffffffu, e, o);
            if (lane == 0) {
                out[n] = (float)best;
                out[2 * NROWS + n] = -logf(e);
            }
        }
        __syncthreads();
    }
}

// ---------------- launch ----------------
extern "C" void kernel_launch(void* const* d_in, const int* in_sizes, int n_in,
                              void* d_out, int out_size) {
    const float* features = (const float*)d_in[0];
    const float* episode_starts = (const float*)d_in[1];
    const float* h_pi = (const float*)d_in[2];
    const float* c_pi = (const float*)d_in[3];
    const float* h_vf = (const float*)d_in[4];
    const float* c_vf = (const float*)d_in[5];
    const float* W_feat = (const float*)d_in[6];
    const float* b_feat = (const float*)d_in[7];
    const float* W_emb = (const float*)d_in[8];
    const float* b_emb = (const float*)d_in[9];
    const float* W_ih = (const float*)d_in[10];
    const float* W_hh = (const float*)d_in[11];
    const float* b_ih = (const float*)d_in[12];
    const float* b_hh = (const float*)d_in[13];
    const float* Wp1 = (const float*)d_in[14];
    const float* bp1 = (const float*)d_in[15];
    const float* Wp2 = (const float*)d_in[16];
    const float* bp2 = (const float*)d_in[17];
    const float* Wv1 = (const float*)d_in[18];
    const float* bv1 = (const float*)d_in[19];
    const float* Wv2 = (const float*)d_in[20];
    const float* bv2 = (const float*)d_in[21];
    float* out = (float*)d_out;

    float *p_WcatHi, *p_WcatLo, *p_bcat, *p_Wp2T, *p_f1, *p_opi, *p_xg, *p_hs;
    float *p_Wp1Hi, *p_Wp1Lo, *p_Wv1Hi, *p_Wv1Lo;
    uint4* p_WpH;
    cudaGetSymbolAddress((void**)&p_WcatHi, g_WcatHi);
    cudaGetSymbolAddress((void**)&p_WcatLo, g_WcatLo);
    cudaGetSymbolAddress((void**)&p_bcat, g_bcat);
    cudaGetSymbolAddress((void**)&p_WpH, g_WpackH);
    cudaGetSymbolAddress((void**)&p_Wp2T, g_Wp2T);
    cudaGetSymbolAddress((void**)&p_Wp1Hi, g_Wp1Hi);
    cudaGetSymbolAddress((void**)&p_Wp1Lo, g_Wp1Lo);
    cudaGetSymbolAddress((void**)&p_Wv1Hi, g_Wv1Hi);
    cudaGetSymbolAddress((void**)&p_Wv1Lo, g_Wv1Lo);
    cudaGetSymbolAddress((void**)&p_f1, g_f1);
    cudaGetSymbolAddress((void**)&p_opi, g_opi);
    cudaGetSymbolAddress((void**)&p_xg, g_xg);
    cudaGetSymbolAddress((void**)&p_hs, g_hs);
    float* p_HP = p_xg;
    float* p_HV = p_xg + (size_t)NROWS * 512;

    cudaFuncSetAttribute(head_final, cudaFuncAttributeMaxDynamicSharedMemorySize, 81920);

    prep_kernel<<<2048, 256>>>(W_feat, b_feat, W_emb, b_emb, W_ih, W_hh, b_ih, b_hh, Wp2);
    wsplit_kernel<<<4096, 256>>>(Wp1, Wv1);
    zero_ctr<<<1, 32>>>();
    hpi_kernel<<<NSEQ, 256>>>(episode_starts, h_pi, c_pi, out);

    // pre-GEMM: features(N,256) @ Wcat(2048,256)^T -> f1 / opi / xg
    mma_gemm<0><<<dim3(2048 / 128, NROWS / 128), 256>>>(
        features, features, 256, 256, 256, 256, p_WcatHi, p_WcatLo, 256, p_bcat, p_f1, p_opi, p_xg);

    lstm_kernel<<<NSEQ, 256>>>(episode_starts, h_vf, c_vf, p_WpH, p_xg, p_hs, out);

    // heads: latent(1024 = f1[768] ++ other[256]) -> relu(512)
    mma_gemm<1><<<dim3(512 / 128, NROWS / 128), 256>>>(
        p_f1, p_opi, 768, 1024, 768, 256, p_Wp1Hi, p_Wp1Lo, 1024, bp1, p_HP, nullptr, nullptr);
    mma_gemm<1><<<dim3(512 / 128, NROWS / 128), 256>>>(
        p_f1, p_hs, 768, 1024, 768, 256, p_Wv1Hi, p_Wv1Lo, 1024, bv1, p_HV, nullptr, nullptr);

    head_final<<<NROWS / 8, 256, 81920>>>(p_HP, p_HV, bp2, Wv2, bv2, p_Wp2T, out);
    fixup_kernel<<<128, 256>>>(features, W_feat, b_feat, W_emb, b_emb, Wp1, bp1, Wp2, bp2, out);
}

// round 7
// speedup vs baseline: 2.0354x; 2.0354x over previous
#include <cuda_runtime.h>
#include <cuda_bf16.h>
#include <cstdint>
#include <cstddef>

#define NROWS 131072
#define NSEQ 64
#define TSTEPS 2048

// ---------------- scratch ----------------
__device__ __align__(16) float g_WcatHi[2048 * 256];
__device__ __align__(16) float g_WcatLo[2048 * 256];
__device__ float g_bcat[2048];
__device__ __align__(16) uint4 g_WpackH[128 * 256];
__device__ float g_Wp2T[512 * 32];
__device__ __align__(16) float g_Wp1Hi[512 * 1024];
__device__ __align__(16) float g_Wp1Lo[512 * 1024];
__device__ __align__(16) float g_Wv1Hi[512 * 1024];
__device__ __align__(16) float g_Wv1Lo[512 * 1024];
__device__ __align__(16) float g_f1[(size_t)NROWS * 768];
__device__ __align__(16) float g_opi[(size_t)NROWS * 256];
__device__ __align__(16) float g_xg[(size_t)NROWS * 1024];   // reused as HP/HV after LSTM
__device__ __align__(16) float g_hs[(size_t)NROWS * 256];
__device__ int g_fixctr;
__device__ int g_fixlist[65536];

// ---------------- helpers ----------------
__device__ __forceinline__ unsigned long long ffma2(unsigned long long a, unsigned long long b, unsigned long long c) {
    asm("fma.rn.f32x2 %0, %1, %2, %3;" : "=l"(c) : "l"(a), "l"(b), "l"(c));
    return c;
}
__device__ __forceinline__ void unpack2(unsigned long long v, float& a, float& b) {
    asm("mov.b64 {%0, %1}, %2;" : "=f"(a), "=f"(b) : "l"(v));
}
__device__ __forceinline__ unsigned long long pack2b(unsigned lo, unsigned hi) {
    unsigned long long r;
    asm("mov.b64 %0, {%1, %2};" : "=l"(r) : "r"(lo), "r"(hi));
    return r;
}
__device__ __forceinline__ unsigned long long bfexp(unsigned r) {
    return pack2b(r << 16, r & 0xffff0000u);
}
__device__ __forceinline__ float sigf(float x) { return __fdividef(1.f, 1.f + __expf(-x)); }
__device__ __forceinline__ float tanha(float x) {
    float y;
    asm("tanh.approx.f32 %0, %1;" : "=f"(y) : "f"(x));
    return y;
}
__device__ __forceinline__ void split_tf32(float x, uint32_t& h, uint32_t& l) {
    asm("cvt.rna.tf32.f32 %0, %1;" : "=r"(h) : "f"(x));
    float lo = x - __uint_as_float(h);
    asm("cvt.rna.tf32.f32 %0, %1;" : "=r"(l) : "f"(lo));
}
__device__ __forceinline__ void mma_tf32(float* d, const uint32_t* a, const uint32_t* b) {
    asm volatile(
        "mma.sync.aligned.m16n8k8.row.col.f32.tf32.tf32.f32 "
        "{%0,%1,%2,%3}, {%4,%5,%6,%7}, {%8,%9}, {%0,%1,%2,%3};"
        : "+f"(d[0]), "+f"(d[1]), "+f"(d[2]), "+f"(d[3])
        : "r"(a[0]), "r"(a[1]), "r"(a[2]), "r"(a[3]), "r"(b[0]), "r"(b[1]));
}

// ---------------- prep ----------------
__global__ void prep_kernel(const float* __restrict__ W_feat, const float* __restrict__ b_feat,
                            const float* __restrict__ W_emb, const float* __restrict__ b_emb,
                            const float* __restrict__ W_ih, const float* __restrict__ W_hh,
                            const float* __restrict__ b_ih, const float* __restrict__ b_hh,
                            const float* __restrict__ Wp2) {
    int i = blockIdx.x * 256 + threadIdx.x;   // up to 524288
    {
        int r = i >> 8;
        float wv;
        if (r < 768) wv = W_feat[i];
        else if (r < 1024) wv = W_emb[i - 768 * 256];
        else wv = W_ih[i - 1024 * 256];
        uint32_t h, l;
        split_tf32(wv, h, l);
        g_WcatHi[i] = __uint_as_float(h);
        g_WcatLo[i] = __uint_as_float(l);
    }
    if (i < 2048) {
        float b;
        if (i < 768) b = b_feat[i];
        else if (i < 1024) b = b_emb[i - 768];
        else b = b_ih[i - 1024] + b_hh[i - 1024];
        g_bcat[i] = b;
    }
    if (i < 65536) {
        int kk = i >> 8, k = i & 255;
        float wi = W_hh[(0 + k) * 256 + kk];
        float wf = W_hh[(256 + k) * 256 + kk];
        float wg = W_hh[(512 + k) * 256 + kk];
        float wo = W_hh[(768 + k) * 256 + kk];
        __nv_bfloat162 bif = __floats2bfloat162_rn(wi, wf);
        __nv_bfloat162 bgo = __floats2bfloat162_rn(wg, wo);
        unsigned uif = *(unsigned*)&bif;
        unsigned ugo = *(unsigned*)&bgo;
        int kk2 = kk >> 1, half = kk & 1;
        ((uint2*)g_WpackH)[(kk2 << 9) + (k << 1) + half] = make_uint2(uif, ugo);
    }
    if (i < 16384) {
        int j = i >> 5, a = i & 31;
        g_Wp2T[i] = Wp2[a * 512 + j];
    }
}

__global__ void wsplit_kernel(const float* __restrict__ Wp1, const float* __restrict__ Wv1) {
    int i = blockIdx.x * 256 + threadIdx.x;   // up to 1048576
    uint32_t h, l;
    if (i < 524288) {
        split_tf32(Wp1[i], h, l);
        g_Wp1Hi[i] = __uint_as_float(h);
        g_Wp1Lo[i] = __uint_as_float(l);
    } else {
        int j = i - 524288;
        split_tf32(Wv1[j], h, l);
        g_Wv1Hi[j] = __uint_as_float(h);
        g_Wv1Lo[j] = __uint_as_float(l);
    }
}

__global__ void zero_ctr() { if (threadIdx.x == 0) g_fixctr = 0; }

// ---------------- h_pi/c_pi masked passthrough ----------------
__global__ void hpi_kernel(const float* __restrict__ starts, const float* __restrict__ h_pi,
                           const float* __restrict__ c_pi, float* __restrict__ out) {
    int s = blockIdx.x, tid = threadIdx.x;
    __shared__ float red[256];
    float p = 1.f;
    for (int t = tid; t < TSTEPS; t += 256) p *= (1.f - starts[s * TSTEPS + t]);
    red[tid] = p;
    __syncthreads();
    for (int st = 128; st; st >>= 1) {
        if (tid < st) red[tid] *= red[tid + st];
        __syncthreads();
    }
    float m = red[0];
    size_t base = (size_t)3 * NROWS;
    out[base + s * 256 + tid] = h_pi[s * 256 + tid] * m;
    out[base + 16384 + s * 256 + tid] = c_pi[s * 256 + tid] * m;
}

// ---------------- mma.sync tf32-split GEMM ----------------
#define PADK 20

template <int MODE>
__global__ void __launch_bounds__(256, 2) mma_gemm(
    const float* __restrict__ A0, const float* __restrict__ A1,
    int K0, int Ktot, int lda0, int lda1,
    const float* __restrict__ WHi, const float* __restrict__ WLo, int ldw,
    const float* __restrict__ bias,
    float* __restrict__ C0, float* __restrict__ C1, float* __restrict__ C2) {
    __shared__ __align__(16) float smem[4 * 128 * PADK];  // 40960 B
    float* sAh = smem;
    float* sAl = smem + 128 * PADK;
    float* sBh = smem + 2 * 128 * PADK;
    float* sBl = smem + 3 * 128 * PADK;

    int tid = threadIdx.x, lane = tid & 31, wid = tid >> 5;
    int wr = wid >> 2, wc = wid & 3;
    int rowBase = blockIdx.y * 128, colBase = blockIdx.x * 128;

    float acc[4][4][4];
#pragma unroll
    for (int a = 0; a < 4; a++)
#pragma unroll
        for (int b = 0; b < 4; b++)
#pragma unroll
            for (int c = 0; c < 4; c++) acc[a][b][c] = 0.f;

    int rowL = tid >> 1, colL = (tid & 1) * 8;
    const int nK = Ktot / 16;

    for (int kt = 0; kt < nK; kt++) {
        int kb = kt * 16;
        const float* Asrc;
        int lda, kloc;
        if (kb < K0) { Asrc = A0; lda = lda0; kloc = kb; }
        else { Asrc = A1; lda = lda1; kloc = kb - K0; }
        const float* ap = Asrc + (size_t)(rowBase + rowL) * lda + kloc + colL;
        const float* bhp = WHi + (size_t)(colBase + rowL) * ldw + kb + colL;
        const float* blp = WLo + (size_t)(colBase + rowL) * ldw + kb + colL;
#pragma unroll
        for (int q = 0; q < 2; q++) {
            float4 v = *(const float4*)(ap + q * 4);
            uint32_t h0, l0, h1, l1, h2, l2, h3, l3;
            split_tf32(v.x, h0, l0);
            split_tf32(v.y, h1, l1);
            split_tf32(v.z, h2, l2);
            split_tf32(v.w, h3, l3);
            int off = rowL * PADK + colL + q * 4;
            *(uint4*)&sAh[off] = make_uint4(h0, h1, h2, h3);
            *(uint4*)&sAl[off] = make_uint4(l0, l1, l2, l3);
        }
#pragma unroll
        for (int q = 0; q < 2; q++) {
            int off = rowL * PADK + colL + q * 4;
            *(float4*)&sBh[off] = *(const float4*)(bhp + q * 4);
            *(float4*)&sBl[off] = *(const float4*)(blp + q * 4);
        }
        __syncthreads();

#pragma unroll
        for (int ks = 0; ks < 2; ks++) {
            int kcol = ks * 8 + (lane & 3);
            uint32_t bh4[4][2], bl4[4][2];
#pragma unroll
            for (int ni = 0; ni < 4; ni++) {
                int nrow = wc * 32 + ni * 8 + (lane >> 2);
                bh4[ni][0] = __float_as_uint(sBh[nrow * PADK + kcol]);
                bh4[ni][1] = __float_as_uint(sBh[nrow * PADK + kcol + 4]);
                bl4[ni][0] = __float_as_uint(sBl[nrow * PADK + kcol]);
                bl4[ni][1] = __float_as_uint(sBl[nrow * PADK + kcol + 4]);
            }
#pragma unroll
            for (int mi = 0; mi < 4; mi++) {
                int mrow = wr * 64 + mi * 16 + (lane >> 2);
                uint32_t ah[4], al[4];
                ah[0] = __float_as_uint(sAh[mrow * PADK + kcol]);
                ah[1] = __float_as_uint(sAh[(mrow + 8) * PADK + kcol]);
                ah[2] = __float_as_uint(sAh[mrow * PADK + kcol + 4]);
                ah[3] = __float_as_uint(sAh[(mrow + 8) * PADK + kcol + 4]);
                al[0] = __float_as_uint(sAl[mrow * PADK + kcol]);
                al[1] = __float_as_uint(sAl[(mrow + 8) * PADK + kcol]);
                al[2] = __float_as_uint(sAl[mrow * PADK + kcol + 4]);
                al[3] = __float_as_uint(sAl[(mrow + 8) * PADK + kcol + 4]);
#pragma unroll
                for (int ni = 0; ni < 4; ni++) {
                    mma_tf32(acc[mi][ni], al, bh4[ni]);
                    mma_tf32(acc[mi][ni], ah, bl4[ni]);
                    mma_tf32(acc[mi][ni], ah, bh4[ni]);
                }
            }
        }
        __syncthreads();
    }

    // ---- epilogue: stage through smem (reuse operand buffers), 2 half-phases ----
    float* T = smem;   // 64 x 132
#pragma unroll
    for (int ph = 0; ph < 2; ph++) {
        if (wr == ph) {
#pragma unroll
            for (int mi = 0; mi < 4; mi++) {
#pragma unroll
                for (int ni = 0; ni < 4; ni++) {
                    int r0 = mi * 16 + (lane >> 2);
                    int cc = wc * 32 + ni * 8 + (lane & 3) * 2;
                    *(float2*)&T[r0 * 132 + cc] = make_float2(acc[mi][ni][0], acc[mi][ni][1]);
                    *(float2*)&T[(r0 + 8) * 132 + cc] = make_float2(acc[mi][ni][2], acc[mi][ni][3]);
                }
            }
        }
        __syncthreads();
#pragma unroll
        for (int i = 0; i < 8; i++) {
            int lin = tid + i * 256;
            int rr = lin >> 5, c4 = (lin & 31) * 4;
            float4 v = *(float4*)&T[rr * 132 + c4];
            float4 bv = *(const float4*)&bias[colBase + c4];
            v.x += bv.x; v.y += bv.y; v.z += bv.z; v.w += bv.w;
            int n = rowBase + ph * 64 + rr;
            int c = colBase + c4;
            if (MODE == 1) {
                v.x = fmaxf(v.x, 0.f); v.y = fmaxf(v.y, 0.f); v.z = fmaxf(v.z, 0.f); v.w = fmaxf(v.w, 0.f);
                *(float4*)&C0[((size_t)n << 9) + c] = v;
            } else {
                if (colBase < 768) *(float4*)&C0[(size_t)n * 768 + c] = v;
                else if (colBase < 1024) *(float4*)&C1[(size_t)n * 256 + (c - 768)] = v;
                else {
                    int sq = n >> 11, tt = n & 2047;
                    *(float4*)&C2[((size_t)((tt << 6) | sq) << 10) + (c - 1024)] = v;
                }
            }
        }
        __syncthreads();
    }
}

// ---------------- LSTM scan: one CTA per sequence, 1024 threads, 4-way k-split ----------------
__global__ void __launch_bounds__(1024) lstm_kernel(
    const float* __restrict__ starts, const float* __restrict__ h0,
    const float* __restrict__ c0v, const uint4* __restrict__ WpH,
    const float* __restrict__ xg, float* __restrict__ hs,
    float* __restrict__ out) {
    int s = blockIdx.x;
    int tid = threadIdx.x;
    int k = tid & 255;
    int j = tid >> 8;            // 0..3  -> kk2 slice [32j, 32j+32)
    __shared__ __align__(16) float2 hbuf[256];
    __shared__ __align__(16) float4 psum[4][256];

    float c = 0.f, hn = 0.f;
    if (j == 0) {
        c = c0v[s * 256 + k];
        float h = h0[s * 256 + k];
        hbuf[k] = make_float2(h, h);
    }
    __syncthreads();

    const uint4* __restrict__ wbase = WpH + (j << 13);   // j*32 kk2 * 256
    const ulonglong2* hb2 = (const ulonglong2*)hbuf;

    for (int t = 0; t < TSTEPS; t++) {
        float m = 1.0f - starts[s * TSTEPS + t];
        unsigned long long aif = 0ULL, ago = 0ULL;
#pragma unroll 8
        for (int q = 0; q < 32; q++) {
            uint4 w = wbase[(q << 8) + k];
            ulonglong2 hh = hb2[(j << 5) + q];
            aif = ffma2(bfexp(w.x), hh.x, aif);
            ago = ffma2(bfexp(w.y), hh.x, ago);
            aif = ffma2(bfexp(w.z), hh.y, aif);
            ago = ffma2(bfexp(w.w), hh.y, ago);
        }
        float p0, p1, p2, p3;
        unpack2(aif, p0, p1);
        unpack2(ago, p2, p3);
        psum[j][k] = make_float4(p0, p1, p2, p3);
        __syncthreads();
        if (j == 0) {
            float4 q1 = psum[1][k];
            float4 q2 = psum[2][k];
            float4 q3 = psum[3][k];
            float di = p0 + q1.x + q2.x + q3.x;
            float df = p1 + q1.y + q2.y + q3.y;
            float dg = p2 + q1.z + q2.z + q3.z;
            float dq = p3 + q1.w + q2.w + q3.w;
            const float* xgp = xg + ((size_t)(t * 64 + s) << 10);
            float gi = xgp[k] + m * di;
            float gf = xgp[256 + k] + m * df;
            float gg = xgp[512 + k] + m * dg;
            float go = xgp[768 + k] + m * dq;
            c *= m;
            c = sigf(gf) * c + sigf(gi) * tanha(gg);
            hn = sigf(go) * tanha(c);
            hs[((size_t)s * TSTEPS + t) * 256 + k] = hn;
            hbuf[k] = make_float2(hn, hn);
        }
        __syncthreads();
    }
    if (j == 0) {
        size_t base = (size_t)3 * NROWS;
        out[base + 32768 + s * 256 + k] = hn;
        out[base + 49152 + s * 256 + k] = c;
    }
}

// ---------------- final: logits, argmax, log_prob, value, near-tie flag ----------------
__global__ void __launch_bounds__(256) head_final(
    const float* __restrict__ HP, const float* __restrict__ HV,
    const float* __restrict__ bp2, const float* __restrict__ Wv2,
    const float* __restrict__ bv2, const float* __restrict__ Wp2T,
    float* __restrict__ out) {
    extern __shared__ float sm[];
    float* sW = sm;            // 16384
    float* sRow = sm + 16384;  // 8*512
    int tid = threadIdx.x, lane = tid & 31, w = tid >> 5;
    for (int i = tid; i < 16384; i += 256) sW[i] = Wp2T[i];
    __syncthreads();
    int n = blockIdx.x * 8 + w;

#pragma unroll
    for (int i = 0; i < 16; i++) sRow[w * 512 + i * 32 + lane] = HP[((size_t)n << 9) + i * 32 + lane];
    __syncwarp();

    float acc = bp2[lane];
    const float* r = &sRow[w * 512];
#pragma unroll 8
    for (int j = 0; j < 512; j++) acc = fmaf(sW[j * 32 + lane], r[j], acc);

    float vacc = 0.f;
#pragma unroll
    for (int i = 0; i < 16; i++) vacc = fmaf(Wv2[i * 32 + lane], HV[((size_t)n << 9) + i * 32 + lane], vacc);
#pragma unroll
    for (int o = 16; o; o >>= 1) vacc += __shfl_xor_sync(0xffffffffu, vacc, o);

    float l = acc;
    float mx = l;
#pragma unroll
    for (int o = 16; o; o >>= 1) mx = fmaxf(mx, __shfl_xor_sync(0xffffffffu, mx, o));
    int best = (l == mx) ? lane : 64;
#pragma unroll
    for (int o = 16; o; o >>= 1) best = min(best, __shfl_xor_sync(0xffffffffu, best, o));
    float e = expf(l - mx);
#pragma unroll
    for (int o = 16; o; o >>= 1) e += __shfl_xor_sync(0xffffffffu, e, o);

    // second max (excluding the argmax lane) for near-tie detection
    float lnb = (lane == best) ? -1e30f : l;
#pragma unroll
    for (int o = 16; o; o >>= 1) lnb = fmaxf(lnb, __shfl_xor_sync(0xffffffffu, lnb, o));

    if (lane == 0) {
        out[n] = (float)best;
        out[NROWS + n] = vacc + bv2[0];
        out[2 * NROWS + n] = -logf(e);
        if (mx - lnb < 1e-4f) {
            int id = atomicAdd(&g_fixctr, 1);
            if (id < 65536) g_fixlist[id] = n;
        }
    }
}

// ---------------- fixup: exact fp32 policy chain for near-tie rows ----------------
__global__ void __launch_bounds__(256) fixup_kernel(
    const float* __restrict__ features,
    const float* __restrict__ W_feat, const float* __restrict__ b_feat,
    const float* __restrict__ W_emb, const float* __restrict__ b_emb,
    const float* __restrict__ Wp1, const float* __restrict__ bp1,
    const float* __restrict__ Wp2, const float* __restrict__ bp2,
    float* __restrict__ out) {
    __shared__ float sx[256];
    __shared__ float lat[1024];
    __shared__ float hp[512];
    __shared__ float lg[32];
    int tid = threadIdx.x, lane = tid & 31, w = tid >> 5;
    int cnt = g_fixctr;
    if (cnt > 65536) cnt = 65536;
    for (int idx = blockIdx.x; idx < cnt; idx += gridDim.x) {
        int n = g_fixlist[idx];
        sx[tid] = features[(size_t)n * 256 + tid];
        __syncthreads();
#pragma unroll
        for (int q = 0; q < 4; q++) {
            int j = tid + q * 256;
            const float* wr;
            float a;
            if (j < 768) { wr = W_feat + (size_t)j * 256; a = b_feat[j]; }
            else { wr = W_emb + (size_t)(j - 768) * 256; a = b_emb[j - 768]; }
            for (int k = 0; k < 256; k++) a = fmaf(wr[k], sx[k], a);
            lat[j] = a;
        }
        __syncthreads();
#pragma unroll
        for (int q = 0; q < 2; q++) {
            int j = tid + q * 256;
            const float* wr = Wp1 + (size_t)j * 1024;
            float a = bp1[j];
            for (int k = 0; k < 1024; k++) a = fmaf(wr[k], lat[k], a);
            hp[j] = fmaxf(a, 0.f);
        }
        __syncthreads();
#pragma unroll
        for (int q = 0; q < 4; q++) {
            int ai = w * 4 + q;
            const float* wr = Wp2 + (size_t)ai * 512;
            float p = 0.f;
            for (int k = lane; k < 512; k += 32) p = fmaf(wr[k], hp[k], p);
#pragma unroll
            for (int o = 16; o; o >>= 1) p += __shfl_xor_sync(0xffffffffu, p, o);
            if (lane == 0) lg[ai] = p + bp2[ai];
        }
        __syncthreads();
        if (w == 0) {
            float l = lg[lane];
            float mx = l;
#pragma unroll
            for (int o = 16; o; o >>= 1) mx = fmaxf(mx, __shfl_xor_sync(0xffffffffu, mx, o));
            int best = (l == mx) ? lane : 64;
#pragma unroll
            for (int o = 16; o; o >>= 1) best = min(best, __shfl_xor_sync(0xffffffffu, best, o));
            float e = expf(l - mx);
#pragma unroll
            for (int o = 16; o; o >>= 1) e += __shfl_xor_sync(0xffffffffu, e, o);
            if (lane == 0) {
                out[n] = (float)best;
                out[2 * NROWS + n] = -logf(e);
            }
        }
        __syncthreads();
    }
}

// ---------------- launch ----------------
extern "C" void kernel_launch(void* const* d_in, const int* in_sizes, int n_in,
                              void* d_out, int out_size) {
    const float* features = (const float*)d_in[0];
    const float* episode_starts = (const float*)d_in[1];
    const float* h_pi = (const float*)d_in[2];
    const float* c_pi = (const float*)d_in[3];
    const float* h_vf = (const float*)d_in[4];
    const float* c_vf = (const float*)d_in[5];
    const float* W_feat = (const float*)d_in[6];
    const float* b_feat = (const float*)d_in[7];
    const float* W_emb = (const float*)d_in[8];
    const float* b_emb = (const float*)d_in[9];
    const float* W_ih = (const float*)d_in[10];
    const float* W_hh = (const float*)d_in[11];
    const float* b_ih = (const float*)d_in[12];
    const float* b_hh = (const float*)d_in[13];
    const float* Wp1 = (const float*)d_in[14];
    const float* bp1 = (const float*)d_in[15];
    const float* Wp2 = (const float*)d_in[16];
    const float* bp2 = (const float*)d_in[17];
    const float* Wv1 = (const float*)d_in[18];
    const float* bv1 = (const float*)d_in[19];
    const float* Wv2 = (const float*)d_in[20];
    const float* bv2 = (const float*)d_in[21];
    float* out = (float*)d_out;

    float *p_WcatHi, *p_WcatLo, *p_bcat, *p_Wp2T, *p_f1, *p_opi, *p_xg, *p_hs;
    float *p_Wp1Hi, *p_Wp1Lo, *p_Wv1Hi, *p_Wv1Lo;
    uint4* p_WpH;
    cudaGetSymbolAddress((void**)&p_WcatHi, g_WcatHi);
    cudaGetSymbolAddress((void**)&p_WcatLo, g_WcatLo);
    cudaGetSymbolAddress((void**)&p_bcat, g_bcat);
    cudaGetSymbolAddress((void**)&p_WpH, g_WpackH);
    cudaGetSymbolAddress((void**)&p_Wp2T, g_Wp2T);
    cudaGetSymbolAddress((void**)&p_Wp1Hi, g_Wp1Hi);
    cudaGetSymbolAddress((void**)&p_Wp1Lo, g_Wp1Lo);
    cudaGetSymbolAddress((void**)&p_Wv1Hi, g_Wv1Hi);
    cudaGetSymbolAddress((void**)&p_Wv1Lo, g_Wv1Lo);
    cudaGetSymbolAddress((void**)&p_f1, g_f1);
    cudaGetSymbolAddress((void**)&p_opi, g_opi);
    cudaGetSymbolAddress((void**)&p_xg, g_xg);
    cudaGetSymbolAddress((void**)&p_hs, g_hs);
    float* p_HP = p_xg;
    float* p_HV = p_xg + (size_t)NROWS * 512;

    cudaFuncSetAttribute(head_final, cudaFuncAttributeMaxDynamicSharedMemorySize, 81920);

    prep_kernel<<<2048, 256>>>(W_feat, b_feat, W_emb, b_emb, W_ih, W_hh, b_ih, b_hh, Wp2);
    wsplit_kernel<<<4096, 256>>>(Wp1, Wv1);
    zero_ctr<<<1, 32>>>();
    hpi_kernel<<<NSEQ, 256>>>(episode_starts, h_pi, c_pi, out);

    // pre-GEMM: features(N,256) @ Wcat(2048,256)^T -> f1 / opi / xg
    mma_gemm<0><<<dim3(2048 / 128, NROWS / 128), 256>>>(
        features, features, 256, 256, 256, 256, p_WcatHi, p_WcatLo, 256, p_bcat, p_f1, p_opi, p_xg);

    lstm_kernel<<<NSEQ, 1024>>>(episode_starts, h_vf, c_vf, p_WpH, p_xg, p_hs, out);

    // heads: latent(1024 = f1[768] ++ other[256]) -> relu(512)
    mma_gemm<1><<<dim3(512 / 128, NROWS / 128), 256>>>(
        p_f1, p_opi, 768, 1024, 768, 256, p_Wp1Hi, p_Wp1Lo, 1024, bp1, p_HP, nullptr, nullptr);
    mma_gemm<1><<<dim3(512 / 128, NROWS / 128), 256>>>(
        p_f1, p_hs, 768, 1024, 768, 256, p_Wv1Hi, p_Wv1Lo, 1024, bv1, p_HV, nullptr, nullptr);

    head_final<<<NROWS / 8, 256, 81920>>>(p_HP, p_HV, bp2, Wv2, bv2, p_Wp2T, out);
    fixup_kernel<<<128, 256>>>(features, W_feat, b_feat, W_emb, b_emb, Wp1, bp1, Wp2, bp2, out);
}